// round 15
// baseline (speedup 1.0000x reference)
#include <cuda_runtime.h>
#include <cuda_fp16.h>
#include <cstdint>

// ---------------------------------------------------------------------------
// PhotonicNeuralNetwork — B=8192, D_in=1024, H=2048, D_out=2, fp32.
// GEMMs on mma.sync fp16 (HMMA k16), single-fp16 A and W (1 MMA per k16),
// 3-stage cp.async pipeline with ONE __syncthreads per K-chunk.
// Layer-2 thermal offset folded exactly in fp32 (tn@W2 matvec -> bias).
// Exact JAX threefry/erfinv noise. Base = passing round-14 kernel.
// ---------------------------------------------------------------------------

#define BATCH 8192
#define HDIM  2048

__device__ __align__(16) float  g_bufB[BATCH * HDIM];
__device__ __align__(16) __half g_A[BATCH * HDIM];
__device__ __align__(16) __half g_W[HDIM * HDIM];
__device__ __align__(16) float g_part[512 * HDIM];
__device__ __align__(16) float g_cs[HDIM];
__device__ __align__(16) float g_thermal2[2][HDIM];
__device__ __align__(16) float g_tn[HDIM];
__device__ __align__(16) float g_colAdd[HDIM];

// ---------------------------------------------------------------------------
// Threefry-2x32, exact JAX round/key schedule.
// ---------------------------------------------------------------------------
__host__ __device__ __forceinline__ uint32_t rotl32(uint32_t x, uint32_t r) {
#if defined(__CUDA_ARCH__)
  return __funnelshift_l(x, x, r);
#else
  return (x << r) | (x >> (32u - r));
#endif
}

__host__ __device__ __forceinline__ void threefry2x32(
    uint32_t k0, uint32_t k1, uint32_t x0, uint32_t x1,
    uint32_t& o0, uint32_t& o1) {
  uint32_t ks2 = 0x1BD11BDAu ^ k0 ^ k1;
  x0 += k0; x1 += k1;
#define TF_ROUND(r) { x0 += x1; x1 = rotl32(x1, r); x1 ^= x0; }
  TF_ROUND(13u) TF_ROUND(15u) TF_ROUND(26u) TF_ROUND(6u)
  x0 += k1;  x1 += ks2 + 1u;
  TF_ROUND(17u) TF_ROUND(29u) TF_ROUND(16u) TF_ROUND(24u)
  x0 += ks2; x1 += k0 + 2u;
  TF_ROUND(13u) TF_ROUND(15u) TF_ROUND(26u) TF_ROUND(6u)
  x0 += k0;  x1 += k1 + 3u;
  TF_ROUND(17u) TF_ROUND(29u) TF_ROUND(16u) TF_ROUND(24u)
  x0 += k1;  x1 += ks2 + 4u;
  TF_ROUND(13u) TF_ROUND(15u) TF_ROUND(26u) TF_ROUND(6u)
  x0 += ks2; x1 += k0 + 5u;
#undef TF_ROUND
  o0 = x0; o1 = x1;
}

__device__ __forceinline__ float xla_erfinv(float x) {
  float w = -log1pf(-x * x);
  float p;
  if (w < 5.0f) {
    w -= 2.5f;
    p = 2.81022636e-08f;
    p = fmaf(p, w, 3.43273939e-07f);
    p = fmaf(p, w, -3.5233877e-06f);
    p = fmaf(p, w, -4.39150654e-06f);
    p = fmaf(p, w, 0.00021858087f);
    p = fmaf(p, w, -0.00125372503f);
    p = fmaf(p, w, -0.00417768164f);
    p = fmaf(p, w, 0.246640727f);
    p = fmaf(p, w, 1.50140941f);
  } else {
    w = sqrtf(w) - 3.0f;
    p = -0.000200214257f;
    p = fmaf(p, w, 0.000100950558f);
    p = fmaf(p, w, 0.00134934322f);
    p = fmaf(p, w, -0.00367342844f);
    p = fmaf(p, w, 0.00573950773f);
    p = fmaf(p, w, -0.0076224613f);
    p = fmaf(p, w, 0.00943887047f);
    p = fmaf(p, w, 1.00167406f);
    p = fmaf(p, w, 2.83297682f);
  }
  return p * x;
}

__device__ __forceinline__ float jax_normal(uint32_t k0, uint32_t k1, uint32_t idx) {
  uint32_t o0, o1;
  threefry2x32(k0, k1, 0u, idx, o0, o1);
  uint32_t bits = o0 ^ o1;
  float f = __uint_as_float((bits >> 9) | 0x3f800000u) - 1.0f;
  const float lo = __uint_as_float(0xBF7FFFFFu);
  float u = fmaxf(fmaf(f, 2.0f, lo), lo);
  return 1.41421354f * xla_erfinv(u);
}

// ---------------------------------------------------------------------------
// PTX helpers (base-sm_100-safe)
// ---------------------------------------------------------------------------
__device__ __forceinline__ uint32_t smem_u32(const void* p) {
  uint32_t a;
  asm("{ .reg .u64 t; cvta.to.shared.u64 t, %1; cvt.u32.u64 %0, t; }"
      : "=r"(a) : "l"(p));
  return a;
}

__device__ __forceinline__ void cp16(uint32_t dst, const void* src) {
  asm volatile("cp.async.cg.shared.global [%0], [%1], 16;"
               :: "r"(dst), "l"(src) : "memory");
}

__device__ __forceinline__ void ldsm_x4(uint32_t* r, uint32_t addr) {
  asm volatile("ldmatrix.sync.aligned.m8n8.x4.shared.b16 {%0,%1,%2,%3}, [%4];"
               : "=r"(r[0]), "=r"(r[1]), "=r"(r[2]), "=r"(r[3]) : "r"(addr));
}

__device__ __forceinline__ void mma_f16(float* d, const uint32_t* a,
                                        const uint32_t* b) {
  asm volatile(
      "mma.sync.aligned.m16n8k16.row.col.f32.f16.f16.f32 "
      "{%0,%1,%2,%3}, {%4,%5,%6,%7}, {%8,%9}, {%0,%1,%2,%3};"
      : "+f"(d[0]), "+f"(d[1]), "+f"(d[2]), "+f"(d[3])
      : "r"(a[0]), "r"(a[1]), "r"(a[2]), "r"(a[3]), "r"(b[0]), "r"(b[1]));
}

// ---------------------------------------------------------------------------
// fp16 converters
// ---------------------------------------------------------------------------
__global__ void convert_w_kernel(const float* __restrict__ W, int n4) {
  int gi = blockIdx.x * blockDim.x + threadIdx.x;
  if (gi >= n4) return;
  float4 v = reinterpret_cast<const float4*>(W)[gi];
  __half2* Wp = reinterpret_cast<__half2*>(g_W);
  Wp[2 * gi]     = __halves2half2(__float2half_rn(v.x), __float2half_rn(v.y));
  Wp[2 * gi + 1] = __halves2half2(__float2half_rn(v.z), __float2half_rn(v.w));
}

__global__ void tanh_in_kernel(const float* __restrict__ x) {
  int gi = blockIdx.x * blockDim.x + threadIdx.x;
  float4 v = reinterpret_cast<const float4*>(x)[gi];
  __half2* A = reinterpret_cast<__half2*>(g_A);
  A[2 * gi]     = __halves2half2(__float2half_rn(tanhf(v.x)),
                                 __float2half_rn(tanhf(v.y)));
  A[2 * gi + 1] = __halves2half2(__float2half_rn(tanhf(v.z)),
                                 __float2half_rn(tanhf(v.w)));
}

// ---------------------------------------------------------------------------
// HMMA GEMM: Y[m,n] = tanh(sum_k A[m,k]*W[n,k] + bias[n]) + 0.02*noise
// CTA 128x256, 512 threads (16 warps, 2x8), warp tile 64x32, BK=64 fp16.
// 3-stage cp.async pipeline, one __syncthreads per chunk.
// ---------------------------------------------------------------------------
#define TM 128
#define TN 256
#define CK 64
#define A_T (128 * 128)                   // 16 KB A tile
#define W_T (256 * 128)                   // 32 KB W tile
#define STAGE_BYTES (A_T + W_T)           // 48 KB
#define N_STAGES 3
#define GEMM_DYN_SMEM (1024 + N_STAGES * STAGE_BYTES)

__global__ void __launch_bounds__(512, 1)
gemm_fp16_kernel(const float* __restrict__ bias, int K,
                 uint32_t nk0, uint32_t nk1) {
  extern __shared__ char dynsmem[];
  __shared__ float sBias[TN];

  const int tid  = threadIdx.x;
  const int wid  = tid >> 5;
  const int lane = tid & 31;
  const int bn   = blockIdx.x * TN;
  const int bm   = blockIdx.y * TM;
  const int wr   = wid & 1;    // 0..1 : 64 rows each
  const int wc   = wid >> 1;   // 0..7 : 32 cols each

  const uint32_t smem = (smem_u32(dynsmem) + 1023u) & ~1023u;

  if (tid < TN) sBias[tid] = bias[bn + tid];

  // stage loader: rows are 128B, XOR swizzle on 16B chunks.
  const int lr = tid >> 3;  // 0..63
  const int lc = tid & 7;
  const uint32_t sw = (uint32_t)((lc ^ (lr & 7)) << 4);
  const __half* Ap = g_A;
  const __half* Wp = g_W;

  auto load_stage = [&](int s, int ck) {
    const uint32_t base = smem + (uint32_t)s * STAGE_BYTES;
    const size_t kcol = (size_t)ck * CK + (size_t)lc * 8;
#pragma unroll
    for (int q = 0; q < 2; ++q) {
      const int r = lr + 64 * q;
      const uint32_t doff = (uint32_t)r * 128u + sw;
      cp16(base + doff, Ap + (size_t)(bm + r) * K + kcol);
    }
    const uint32_t wb = base + A_T;
#pragma unroll
    for (int q = 0; q < 4; ++q) {
      const int r = lr + 64 * q;
      const uint32_t doff = (uint32_t)r * 128u + sw;
      cp16(wb + doff, Wp + (size_t)(bn + r) * K + kcol);
    }
    asm volatile("cp.async.commit_group;" ::: "memory");
  };

  // ldmatrix per-lane addressing (verbatim from the passing round-14 kernel).
  const int aRow = wr * 64 + (lane & 15);
  const int aChk = lane >> 4;
  const uint32_t aSwz = (uint32_t)(lane & 7) << 4;
  const int bRow0 = wc * 32 + ((lane >> 4) << 3) + (lane & 7);
  const int bChk = (lane >> 3) & 1;
  const uint32_t bSwz = (uint32_t)(lane & 7) << 4;

  float acc[4][4][4];
#pragma unroll
  for (int i = 0; i < 4; ++i)
#pragma unroll
    for (int j = 0; j < 4; ++j)
#pragma unroll
      for (int t = 0; t < 4; ++t) acc[i][j][t] = 0.0f;

  const int nch = K / CK;  // 16 or 32 (always >= 2)
  load_stage(0, 0);
  load_stage(1, 1);

  for (int c = 0; c < nch; ++c) {
    const int s = c % N_STAGES;
    // Wait for stage c (allow stage c+1 to remain in flight).
    if (c + 1 < nch) {
      asm volatile("cp.async.wait_group 1;" ::: "memory");
    } else {
      asm volatile("cp.async.wait_group 0;" ::: "memory");
    }
    // Single barrier: stage c visible to all; all warps done reading the
    // slot (c+2) % N_STAGES (== slot of chunk c-1) from the previous iter.
    __syncthreads();
    if (c + 2 < nch) load_stage((c + 2) % N_STAGES, c + 2);

    const uint32_t aB = smem + (uint32_t)s * STAGE_BYTES;
    const uint32_t wB = aB + A_T;

#pragma unroll
    for (int ks = 0; ks < 4; ++ks) {
      const uint32_t aOffC = ((uint32_t)((2 * ks + aChk) << 4)) ^ aSwz;
      const uint32_t bOffC = ((uint32_t)((2 * ks + bChk) << 4)) ^ bSwz;

      uint32_t wh[4][2];
#pragma unroll
      for (int jp = 0; jp < 2; ++jp) {
        const uint32_t off = (uint32_t)(bRow0 + jp * 16) * 128u + bOffC;
        ldsm_x4(&wh[2 * jp][0], wB + off);
      }
      uint32_t af[4][4];
#pragma unroll
      for (int i = 0; i < 4; ++i) {
        const uint32_t off = (uint32_t)(aRow + i * 16) * 128u + aOffC;
        ldsm_x4(af[i], aB + off);
      }
#pragma unroll
      for (int i = 0; i < 4; ++i)
#pragma unroll
        for (int j = 0; j < 4; ++j) mma_f16(acc[i][j], af[i], wh[j]);
    }
  }

  // epilogue: bias + tanh + exact JAX noise
  const int r0 = bm + wr * 64 + (lane >> 2);
  const int c0l = wc * 32 + 2 * (lane & 3);
#pragma unroll
  for (int i = 0; i < 4; ++i) {
#pragma unroll
    for (int j = 0; j < 4; ++j) {
      const int cc = c0l + j * 8;
      const int cg = bn + cc;
#pragma unroll
      for (int hrow = 0; hrow < 2; ++hrow) {
        const int m = r0 + i * 16 + hrow * 8;
        const uint32_t nb = (uint32_t)m * 2048u + (uint32_t)cg;
        float v0 = acc[i][j][2 * hrow]     + sBias[cc];
        float v1 = acc[i][j][2 * hrow + 1] + sBias[cc + 1];
        v0 = tanhf(v0) + jax_normal(nk0, nk1, nb)     * 0.02f;
        v1 = tanhf(v1) + jax_normal(nk0, nk1, nb + 1) * 0.02f;
        *reinterpret_cast<float2*>(g_bufB + (size_t)m * HDIM + cg) =
            make_float2(v0, v1);
      }
    }
  }
}

// ---------------------------------------------------------------------------
// colsum two-phase (deterministic) — unchanged.
// ---------------------------------------------------------------------------
__global__ void colsum_part_kernel() {
  const int b = blockIdx.x;
  const int t = threadIdx.x;
  const float* base = g_bufB + (size_t)b * 16 * HDIM;
#pragma unroll
  for (int p = 0; p < 8; ++p) {
    const int c = t + 256 * p;
    float s = 0.0f;
#pragma unroll
    for (int r = 0; r < 16; ++r) s += fabsf(base[(size_t)r * HDIM + c]);
    g_part[b * HDIM + c] = s;
  }
}

__global__ void colsum_reduce_kernel() {
  const int c = blockIdx.x * 256 + threadIdx.x;
  float s = 0.0f;
  for (int p = 0; p < 512; ++p) s += g_part[p * HDIM + c];
  g_cs[c] = s;
}

// ---------------------------------------------------------------------------
// thermal EMA (ping-pong) fused with the crosstalk matvec — unchanged.
// ---------------------------------------------------------------------------
__global__ void thermal_matvec_kernel(int cur, int first) {
  __shared__ float th[HDIM];
  __shared__ float rec[HDIM];
  const int tid = threadIdx.x;  // 128
  const int prev = cur ^ 1;
  for (int i = tid; i < HDIM; i += 128) {
    float lt = g_cs[i] * 0.05f;
    float tv = first ? (0.3f * lt) : (0.7f * g_thermal2[prev][i] + 0.3f * lt);
    th[i] = tv;
    if (blockIdx.x == 0) g_thermal2[cur][i] = tv;
    float d = (float)i;
    rec[i] = (i == 0) ? 0.0f : (1.0f / (d * d));
  }
  __syncthreads();
  const int j = blockIdx.x * 128 + tid;
  float acc = 0.0f;
  for (int i = 0; i < HDIM; ++i) {
    int d = i - j; d = d < 0 ? -d : d;
    acc += th[i] * rec[d];
  }
  g_tn[j] = acc * 0.05f;
}

// colAdd[n] = b[n] + sum_h tn[h]*W[n,h]  (exact fp32 thermal-offset folding).
__global__ void tnw_kernel(const float* __restrict__ W,
                           const float* __restrict__ b) {
  const int wid = threadIdx.x >> 5;
  const int lane = threadIdx.x & 31;
  const int n = blockIdx.x * 8 + wid;
  const float* row = W + (size_t)n * HDIM;
  float s = 0.0f;
  for (int h = lane; h < HDIM; h += 32) s += g_tn[h] * row[h];
#pragma unroll
  for (int o = 16; o > 0; o >>= 1) s += __shfl_xor_sync(0xFFFFFFFFu, s, o);
  if (lane == 0) g_colAdd[n] = s + b[n];
}

// ---------------------------------------------------------------------------
// finalize (layer 0): z = y + tn; phase noise; (x - tn) -> single fp16 A.
// ---------------------------------------------------------------------------
__global__ void finalize_kernel(uint32_t kp0, uint32_t kp1) {
  const int gi = blockIdx.x * blockDim.x + threadIdx.x;
  const int idx = gi << 2;
  float4 y = *reinterpret_cast<const float4*>(g_bufB + idx);
  float4 t = *reinterpret_cast<const float4*>(g_tn + (idx & 2047));
  float v[4] = {y.x, y.y, y.z, y.w};
  float tv[4] = {t.x, t.y, t.z, t.w};
  __half h[4];
#pragma unroll
  for (int c = 0; c < 4; ++c) {
    float z = v[c] + tv[c];
    float ph = jax_normal(kp0, kp1, (uint32_t)(idx + c)) * 0.03f;
    float xx = z + (z * cosf(ph) - z) * 0.03f;
    h[c] = __float2half_rn(xx - tv[c]);
  }
  __half2* A = reinterpret_cast<__half2*>(g_A);
  A[2 * gi]     = __halves2half2(h[0], h[1]);
  A[2 * gi + 1] = __halves2half2(h[2], h[3]);
}

// ---------------------------------------------------------------------------
// finalize (layer 1) fused with output GEMM (D_out=2) — unchanged.
// ---------------------------------------------------------------------------
__global__ void __launch_bounds__(256)
finalize_out_kernel(const float* __restrict__ Wout,
                    const float* __restrict__ bout,
                    float* __restrict__ out,
                    uint32_t kp0, uint32_t kp1) {
  const int b = blockIdx.x;
  const int tid = threadIdx.x;
  const float* row = g_bufB + (size_t)b * 2048;
  float a0 = 0.0f, a1 = 0.0f;
#pragma unroll
  for (int q = 0; q < 2; ++q) {
    const int h = (tid + q * 256) * 4;
    float4 y  = *reinterpret_cast<const float4*>(row + h);
    float4 t  = *reinterpret_cast<const float4*>(g_tn + h);
    float4 w0 = *reinterpret_cast<const float4*>(Wout + h);
    float4 w1 = *reinterpret_cast<const float4*>(Wout + 2048 + h);
    float yv[4] = {y.x, y.y, y.z, y.w};
    float tv[4] = {t.x, t.y, t.z, t.w};
    float w0v[4] = {w0.x, w0.y, w0.z, w0.w};
    float w1v[4] = {w1.x, w1.y, w1.z, w1.w};
#pragma unroll
    for (int c = 0; c < 4; ++c) {
      float xx = yv[c] + tv[c];
      float ph = jax_normal(kp0, kp1, (uint32_t)(b * 2048 + h + c)) * 0.03f;
      xx = xx + (xx * cosf(ph) - xx) * 0.03f;
      a0 += xx * w0v[c];
      a1 += xx * w1v[c];
    }
  }
  __shared__ float s0[256];
  __shared__ float s1[256];
  s0[tid] = a0; s1[tid] = a1;
  __syncthreads();
#pragma unroll
  for (int off = 128; off > 0; off >>= 1) {
    if (tid < off) { s0[tid] += s0[tid + off]; s1[tid] += s1[tid + off]; }
    __syncthreads();
  }
  if (tid == 0) {
    out[2 * b + 0] = s0[0] + bout[0];
    out[2 * b + 1] = s1[0] + bout[1];
  }
}

// ---------------------------------------------------------------------------
// Launch
// ---------------------------------------------------------------------------
extern "C" void kernel_launch(void* const* d_in, const int* in_sizes, int n_in,
                              void* d_out, int out_size) {
  (void)in_sizes; (void)n_in; (void)out_size;
  const float* x    = (const float*)d_in[0];
  const float* W1   = (const float*)d_in[1];
  const float* b1   = (const float*)d_in[2];
  const float* W2   = (const float*)d_in[3];
  const float* b2   = (const float*)d_in[4];
  const float* Wout = (const float*)d_in[5];
  const float* bout = (const float*)d_in[6];
  float* out = (float*)d_out;

  cudaFuncSetAttribute(gemm_fp16_kernel,
                       cudaFuncAttributeMaxDynamicSharedMemorySize,
                       GEMM_DYN_SMEM);

  // Device address of g_colAdd (host-side __device__ symbol use is UB).
  float* colAddPtr = nullptr;
  cudaGetSymbolAddress((void**)&colAddPtr, g_colAdd);

  uint32_t kno[2][2], kph[2][2];
  for (int li = 0; li < 2; ++li) {
    threefry2x32(0u, 42u, 0u, (uint32_t)(2 * li),     kno[li][0], kno[li][1]);
    threefry2x32(0u, 42u, 0u, (uint32_t)(2 * li + 1), kph[li][0], kph[li][1]);
  }

  const dim3 ggrid(HDIM / TN, BATCH / TM);  // 8 x 64

  // Layer 0 (K = 1024); bias = b1 (no thermal offset yet).
  convert_w_kernel<<<2048, 256>>>(W1, 2048 * 1024 / 4);
  tanh_in_kernel<<<8192, 256>>>(x);
  gemm_fp16_kernel<<<ggrid, 512, GEMM_DYN_SMEM>>>(b1, 1024,
                                                  kno[0][0], kno[0][1]);
  colsum_part_kernel<<<512, 256>>>();
  colsum_reduce_kernel<<<8, 256>>>();
  thermal_matvec_kernel<<<16, 128>>>(0, 1);
  tnw_kernel<<<256, 256>>>(W2, b2);
  finalize_kernel<<<16384, 256>>>(kph[0][0], kph[0][1]);

  // Layer 1 (K = 2048); bias = b2 + tn@W2^T (exact fp32), A offset-free.
  convert_w_kernel<<<4096, 256>>>(W2, 2048 * 2048 / 4);
  gemm_fp16_kernel<<<ggrid, 512, GEMM_DYN_SMEM>>>(colAddPtr, 2048,
                                                  kno[1][0], kno[1][1]);
  colsum_part_kernel<<<512, 256>>>();
  colsum_reduce_kernel<<<8, 256>>>();
  thermal_matvec_kernel<<<16, 128>>>(1, 0);

  finalize_out_kernel<<<8192, 256>>>(Wout, bout, out, kph[1][0], kph[1][1]);
}

// round 16
// speedup vs baseline: 1.1282x; 1.1282x over previous
#include <cuda_runtime.h>
#include <cuda_fp16.h>
#include <cstdint>

// ---------------------------------------------------------------------------
// PhotonicNeuralNetwork — B=8192, D_in=1024, H=2048, D_out=2, fp32.
// GEMMs on mma.sync fp16 (HMMA k16), single-fp16 A and W, 2-stage cp.async.
// Exact JAX threefry bits; FAST transcendentals around them (noise enters
// scaled by 0.02/0.03 so ~1e-4 math accuracy suffices; tanh fast path is
// ~2e-6 rel). Layer-2 thermal offset folded exactly in fp32 via tn@W2.
// Base = passing round-14 kernel (897us); only the math functions changed.
// ---------------------------------------------------------------------------

#define BATCH 8192
#define HDIM  2048

__device__ __align__(16) float  g_bufB[BATCH * HDIM];
__device__ __align__(16) __half g_A[BATCH * HDIM];
__device__ __align__(16) __half g_W[HDIM * HDIM];
__device__ __align__(16) float g_part[512 * HDIM];
__device__ __align__(16) float g_cs[HDIM];
__device__ __align__(16) float g_thermal2[2][HDIM];
__device__ __align__(16) float g_tn[HDIM];
__device__ __align__(16) float g_colAdd[HDIM];

// ---------------------------------------------------------------------------
// Threefry-2x32, exact JAX round/key schedule (bits must match exactly).
// ---------------------------------------------------------------------------
__host__ __device__ __forceinline__ uint32_t rotl32(uint32_t x, uint32_t r) {
#if defined(__CUDA_ARCH__)
  return __funnelshift_l(x, x, r);
#else
  return (x << r) | (x >> (32u - r));
#endif
}

__host__ __device__ __forceinline__ void threefry2x32(
    uint32_t k0, uint32_t k1, uint32_t x0, uint32_t x1,
    uint32_t& o0, uint32_t& o1) {
  uint32_t ks2 = 0x1BD11BDAu ^ k0 ^ k1;
  x0 += k0; x1 += k1;
#define TF_ROUND(r) { x0 += x1; x1 = rotl32(x1, r); x1 ^= x0; }
  TF_ROUND(13u) TF_ROUND(15u) TF_ROUND(26u) TF_ROUND(6u)
  x0 += k1;  x1 += ks2 + 1u;
  TF_ROUND(17u) TF_ROUND(29u) TF_ROUND(16u) TF_ROUND(24u)
  x0 += ks2; x1 += k0 + 2u;
  TF_ROUND(13u) TF_ROUND(15u) TF_ROUND(26u) TF_ROUND(6u)
  x0 += k0;  x1 += k1 + 3u;
  TF_ROUND(17u) TF_ROUND(29u) TF_ROUND(16u) TF_ROUND(24u)
  x0 += k1;  x1 += ks2 + 4u;
  TF_ROUND(13u) TF_ROUND(15u) TF_ROUND(26u) TF_ROUND(6u)
  x0 += ks2; x1 += k0 + 5u;
#undef TF_ROUND
  o0 = x0; o1 = x1;
}

// Fast erfinv: exact Giles polynomial, fast log (noise tolerance ~1e-2).
__device__ __forceinline__ float fast_erfinv(float x) {
  float w = -__logf(fmaf(x, -x, 1.0f));
  float p;
  if (w < 5.0f) {
    w -= 2.5f;
    p = 2.81022636e-08f;
    p = fmaf(p, w, 3.43273939e-07f);
    p = fmaf(p, w, -3.5233877e-06f);
    p = fmaf(p, w, -4.39150654e-06f);
    p = fmaf(p, w, 0.00021858087f);
    p = fmaf(p, w, -0.00125372503f);
    p = fmaf(p, w, -0.00417768164f);
    p = fmaf(p, w, 0.246640727f);
    p = fmaf(p, w, 1.50140941f);
  } else {
    w = __fsqrt_rn(w) - 3.0f;
    p = -0.000200214257f;
    p = fmaf(p, w, 0.000100950558f);
    p = fmaf(p, w, 0.00134934322f);
    p = fmaf(p, w, -0.00367342844f);
    p = fmaf(p, w, 0.00573950773f);
    p = fmaf(p, w, -0.0076224613f);
    p = fmaf(p, w, 0.00943887047f);
    p = fmaf(p, w, 1.00167406f);
    p = fmaf(p, w, 2.83297682f);
  }
  return p * x;
}

__device__ __forceinline__ float jax_normal(uint32_t k0, uint32_t k1, uint32_t idx) {
  uint32_t o0, o1;
  threefry2x32(k0, k1, 0u, idx, o0, o1);
  uint32_t bits = o0 ^ o1;
  float f = __uint_as_float((bits >> 9) | 0x3f800000u) - 1.0f;
  const float lo = __uint_as_float(0xBF7FFFFFu);
  float u = fmaxf(fmaf(f, 2.0f, lo), lo);
  return 1.41421354f * fast_erfinv(u);
}

// Fast tanh: (1-e)/(1+e), e = exp(-2|x|); rel err ~2e-6.
__device__ __forceinline__ float fast_tanh(float x) {
  float e = __expf(-2.0f * fabsf(x));
  float t = __fdividef(1.0f - e, 1.0f + e);
  return copysignf(t, x);
}

// Fast cos for |p| <= ~0.25: 3-term Taylor, err < 1e-8.
__device__ __forceinline__ float fast_cos_small(float p) {
  float p2 = p * p;
  return fmaf(p2, fmaf(p2, fmaf(p2, -1.388888889e-3f, 4.166666667e-2f),
                       -0.5f), 1.0f);
}

// ---------------------------------------------------------------------------
// PTX helpers (base-sm_100-safe)
// ---------------------------------------------------------------------------
__device__ __forceinline__ uint32_t smem_u32(const void* p) {
  uint32_t a;
  asm("{ .reg .u64 t; cvta.to.shared.u64 t, %1; cvt.u32.u64 %0, t; }"
      : "=r"(a) : "l"(p));
  return a;
}

__device__ __forceinline__ void cp16(uint32_t dst, const void* src) {
  asm volatile("cp.async.cg.shared.global [%0], [%1], 16;"
               :: "r"(dst), "l"(src) : "memory");
}

__device__ __forceinline__ void ldsm_x4(uint32_t* r, uint32_t addr) {
  asm volatile("ldmatrix.sync.aligned.m8n8.x4.shared.b16 {%0,%1,%2,%3}, [%4];"
               : "=r"(r[0]), "=r"(r[1]), "=r"(r[2]), "=r"(r[3]) : "r"(addr));
}

__device__ __forceinline__ void mma_f16(float* d, const uint32_t* a,
                                        const uint32_t* b) {
  asm volatile(
      "mma.sync.aligned.m16n8k16.row.col.f32.f16.f16.f32 "
      "{%0,%1,%2,%3}, {%4,%5,%6,%7}, {%8,%9}, {%0,%1,%2,%3};"
      : "+f"(d[0]), "+f"(d[1]), "+f"(d[2]), "+f"(d[3])
      : "r"(a[0]), "r"(a[1]), "r"(a[2]), "r"(a[3]), "r"(b[0]), "r"(b[1]));
}

// ---------------------------------------------------------------------------
// fp16 converters
// ---------------------------------------------------------------------------
__global__ void convert_w_kernel(const float* __restrict__ W, int n4) {
  int gi = blockIdx.x * blockDim.x + threadIdx.x;
  if (gi >= n4) return;
  float4 v = reinterpret_cast<const float4*>(W)[gi];
  __half2* Wp = reinterpret_cast<__half2*>(g_W);
  Wp[2 * gi]     = __halves2half2(__float2half_rn(v.x), __float2half_rn(v.y));
  Wp[2 * gi + 1] = __halves2half2(__float2half_rn(v.z), __float2half_rn(v.w));
}

__global__ void tanh_in_kernel(const float* __restrict__ x) {
  int gi = blockIdx.x * blockDim.x + threadIdx.x;
  float4 v = reinterpret_cast<const float4*>(x)[gi];
  __half2* A = reinterpret_cast<__half2*>(g_A);
  A[2 * gi]     = __halves2half2(__float2half_rn(fast_tanh(v.x)),
                                 __float2half_rn(fast_tanh(v.y)));
  A[2 * gi + 1] = __halves2half2(__float2half_rn(fast_tanh(v.z)),
                                 __float2half_rn(fast_tanh(v.w)));
}

// ---------------------------------------------------------------------------
// HMMA GEMM: Y[m,n] = tanh(sum_k A[m,k]*W[n,k] + bias[n]) + 0.02*noise
// CTA 128x256, 512 threads (16 warps, 2x8), warp tile 64x32, BK=64 fp16.
// 2-stage cp.async pipeline (round-14 structure; 3-stage measured neutral).
// ---------------------------------------------------------------------------
#define TM 128
#define TN 256
#define CK 64
#define A_T (128 * 128)                   // 16 KB A tile
#define W_T (256 * 128)                   // 32 KB W tile
#define STAGE_BYTES (A_T + W_T)           // 48 KB
#define GEMM_DYN_SMEM (1024 + 2 * STAGE_BYTES)

__global__ void __launch_bounds__(512, 1)
gemm_fp16_kernel(const float* __restrict__ bias, int K,
                 uint32_t nk0, uint32_t nk1) {
  extern __shared__ char dynsmem[];
  __shared__ float sBias[TN];

  const int tid  = threadIdx.x;
  const int wid  = tid >> 5;
  const int lane = tid & 31;
  const int bn   = blockIdx.x * TN;
  const int bm   = blockIdx.y * TM;
  const int wr   = wid & 1;    // 0..1 : 64 rows each
  const int wc   = wid >> 1;   // 0..7 : 32 cols each

  const uint32_t smem = (smem_u32(dynsmem) + 1023u) & ~1023u;

  if (tid < TN) sBias[tid] = bias[bn + tid];

  // stage loader: rows are 128B, XOR swizzle on 16B chunks.
  const int lr = tid >> 3;  // 0..63
  const int lc = tid & 7;
  const uint32_t sw = (uint32_t)((lc ^ (lr & 7)) << 4);
  const __half* Ap = g_A;
  const __half* Wp = g_W;

  auto load_stage = [&](int s, int ck) {
    const uint32_t base = smem + (uint32_t)s * STAGE_BYTES;
    const size_t kcol = (size_t)ck * CK + (size_t)lc * 8;
#pragma unroll
    for (int q = 0; q < 2; ++q) {
      const int r = lr + 64 * q;
      const uint32_t doff = (uint32_t)r * 128u + sw;
      cp16(base + doff, Ap + (size_t)(bm + r) * K + kcol);
    }
    const uint32_t wb = base + A_T;
#pragma unroll
    for (int q = 0; q < 4; ++q) {
      const int r = lr + 64 * q;
      const uint32_t doff = (uint32_t)r * 128u + sw;
      cp16(wb + doff, Wp + (size_t)(bn + r) * K + kcol);
    }
    asm volatile("cp.async.commit_group;" ::: "memory");
  };

  // ldmatrix per-lane addressing (verbatim from the passing round-14 kernel).
  const int aRow = wr * 64 + (lane & 15);
  const int aChk = lane >> 4;
  const uint32_t aSwz = (uint32_t)(lane & 7) << 4;
  const int bRow0 = wc * 32 + ((lane >> 4) << 3) + (lane & 7);
  const int bChk = (lane >> 3) & 1;
  const uint32_t bSwz = (uint32_t)(lane & 7) << 4;

  float acc[4][4][4];
#pragma unroll
  for (int i = 0; i < 4; ++i)
#pragma unroll
    for (int j = 0; j < 4; ++j)
#pragma unroll
      for (int t = 0; t < 4; ++t) acc[i][j][t] = 0.0f;

  const int nch = K / CK;
  load_stage(0, 0);

  for (int c = 0; c < nch; ++c) {
    const int s = c & 1;
    if (c + 1 < nch) {
      load_stage(s ^ 1, c + 1);
      asm volatile("cp.async.wait_group 1;" ::: "memory");
    } else {
      asm volatile("cp.async.wait_group 0;" ::: "memory");
    }
    __syncthreads();

    const uint32_t aB = smem + (uint32_t)s * STAGE_BYTES;
    const uint32_t wB = aB + A_T;

#pragma unroll
    for (int ks = 0; ks < 4; ++ks) {
      const uint32_t aOffC = ((uint32_t)((2 * ks + aChk) << 4)) ^ aSwz;
      const uint32_t bOffC = ((uint32_t)((2 * ks + bChk) << 4)) ^ bSwz;

      uint32_t wh[4][2];
#pragma unroll
      for (int jp = 0; jp < 2; ++jp) {
        const uint32_t off = (uint32_t)(bRow0 + jp * 16) * 128u + bOffC;
        ldsm_x4(&wh[2 * jp][0], wB + off);
      }
      uint32_t af[4][4];
#pragma unroll
      for (int i = 0; i < 4; ++i) {
        const uint32_t off = (uint32_t)(aRow + i * 16) * 128u + aOffC;
        ldsm_x4(af[i], aB + off);
      }
#pragma unroll
      for (int i = 0; i < 4; ++i)
#pragma unroll
        for (int j = 0; j < 4; ++j) mma_f16(acc[i][j], af[i], wh[j]);
    }
    __syncthreads();
  }

  // epilogue: bias + fast tanh + exact JAX noise (fast erfinv)
  const int r0 = bm + wr * 64 + (lane >> 2);
  const int c0l = wc * 32 + 2 * (lane & 3);
#pragma unroll
  for (int i = 0; i < 4; ++i) {
#pragma unroll
    for (int j = 0; j < 4; ++j) {
      const int cc = c0l + j * 8;
      const int cg = bn + cc;
#pragma unroll
      for (int hrow = 0; hrow < 2; ++hrow) {
        const int m = r0 + i * 16 + hrow * 8;
        const uint32_t nb = (uint32_t)m * 2048u + (uint32_t)cg;
        float v0 = acc[i][j][2 * hrow]     + sBias[cc];
        float v1 = acc[i][j][2 * hrow + 1] + sBias[cc + 1];
        v0 = fast_tanh(v0) + jax_normal(nk0, nk1, nb)     * 0.02f;
        v1 = fast_tanh(v1) + jax_normal(nk0, nk1, nb + 1) * 0.02f;
        *reinterpret_cast<float2*>(g_bufB + (size_t)m * HDIM + cg) =
            make_float2(v0, v1);
      }
    }
  }
}

// ---------------------------------------------------------------------------
// colsum two-phase (deterministic) — unchanged.
// ---------------------------------------------------------------------------
__global__ void colsum_part_kernel() {
  const int b = blockIdx.x;
  const int t = threadIdx.x;
  const float* base = g_bufB + (size_t)b * 16 * HDIM;
#pragma unroll
  for (int p = 0; p < 8; ++p) {
    const int c = t + 256 * p;
    float s = 0.0f;
#pragma unroll
    for (int r = 0; r < 16; ++r) s += fabsf(base[(size_t)r * HDIM + c]);
    g_part[b * HDIM + c] = s;
  }
}

__global__ void colsum_reduce_kernel() {
  const int c = blockIdx.x * 256 + threadIdx.x;
  float s = 0.0f;
  for (int p = 0; p < 512; ++p) s += g_part[p * HDIM + c];
  g_cs[c] = s;
}

// ---------------------------------------------------------------------------
// thermal EMA (ping-pong) fused with the crosstalk matvec — unchanged.
// ---------------------------------------------------------------------------
__global__ void thermal_matvec_kernel(int cur, int first) {
  __shared__ float th[HDIM];
  __shared__ float rec[HDIM];
  const int tid = threadIdx.x;  // 128
  const int prev = cur ^ 1;
  for (int i = tid; i < HDIM; i += 128) {
    float lt = g_cs[i] * 0.05f;
    float tv = first ? (0.3f * lt) : (0.7f * g_thermal2[prev][i] + 0.3f * lt);
    th[i] = tv;
    if (blockIdx.x == 0) g_thermal2[cur][i] = tv;
    float d = (float)i;
    rec[i] = (i == 0) ? 0.0f : (1.0f / (d * d));
  }
  __syncthreads();
  const int j = blockIdx.x * 128 + tid;
  float acc = 0.0f;
  for (int i = 0; i < HDIM; ++i) {
    int d = i - j; d = d < 0 ? -d : d;
    acc += th[i] * rec[d];
  }
  g_tn[j] = acc * 0.05f;
}

// colAdd[n] = b[n] + sum_h tn[h]*W[n,h]  (exact fp32 thermal-offset folding).
__global__ void tnw_kernel(const float* __restrict__ W,
                           const float* __restrict__ b) {
  const int wid = threadIdx.x >> 5;
  const int lane = threadIdx.x & 31;
  const int n = blockIdx.x * 8 + wid;
  const float* row = W + (size_t)n * HDIM;
  float s = 0.0f;
  for (int h = lane; h < HDIM; h += 32) s += g_tn[h] * row[h];
#pragma unroll
  for (int o = 16; o > 0; o >>= 1) s += __shfl_xor_sync(0xFFFFFFFFu, s, o);
  if (lane == 0) g_colAdd[n] = s + b[n];
}

// ---------------------------------------------------------------------------
// finalize (layer 0): z = y + tn; phase noise (fast cos); -> fp16 A.
// ---------------------------------------------------------------------------
__global__ void finalize_kernel(uint32_t kp0, uint32_t kp1) {
  const int gi = blockIdx.x * blockDim.x + threadIdx.x;
  const int idx = gi << 2;
  float4 y = *reinterpret_cast<const float4*>(g_bufB + idx);
  float4 t = *reinterpret_cast<const float4*>(g_tn + (idx & 2047));
  float v[4] = {y.x, y.y, y.z, y.w};
  float tv[4] = {t.x, t.y, t.z, t.w};
  __half h[4];
#pragma unroll
  for (int c = 0; c < 4; ++c) {
    float z = v[c] + tv[c];
    float ph = jax_normal(kp0, kp1, (uint32_t)(idx + c)) * 0.03f;
    float xx = z + (z * fast_cos_small(ph) - z) * 0.03f;
    h[c] = __float2half_rn(xx - tv[c]);
  }
  __half2* A = reinterpret_cast<__half2*>(g_A);
  A[2 * gi]     = __halves2half2(h[0], h[1]);
  A[2 * gi + 1] = __halves2half2(h[2], h[3]);
}

// ---------------------------------------------------------------------------
// finalize (layer 1) fused with output GEMM (D_out=2).
// ---------------------------------------------------------------------------
__global__ void __launch_bounds__(256)
finalize_out_kernel(const float* __restrict__ Wout,
                    const float* __restrict__ bout,
                    float* __restrict__ out,
                    uint32_t kp0, uint32_t kp1) {
  const int b = blockIdx.x;
  const int tid = threadIdx.x;
  const float* row = g_bufB + (size_t)b * 2048;
  float a0 = 0.0f, a1 = 0.0f;
#pragma unroll
  for (int q = 0; q < 2; ++q) {
    const int h = (tid + q * 256) * 4;
    float4 y  = *reinterpret_cast<const float4*>(row + h);
    float4 t  = *reinterpret_cast<const float4*>(g_tn + h);
    float4 w0 = *reinterpret_cast<const float4*>(Wout + h);
    float4 w1 = *reinterpret_cast<const float4*>(Wout + 2048 + h);
    float yv[4] = {y.x, y.y, y.z, y.w};
    float tv[4] = {t.x, t.y, t.z, t.w};
    float w0v[4] = {w0.x, w0.y, w0.z, w0.w};
    float w1v[4] = {w1.x, w1.y, w1.z, w1.w};
#pragma unroll
    for (int c = 0; c < 4; ++c) {
      float xx = yv[c] + tv[c];
      float ph = jax_normal(kp0, kp1, (uint32_t)(b * 2048 + h + c)) * 0.03f;
      xx = xx + (xx * fast_cos_small(ph) - xx) * 0.03f;
      a0 += xx * w0v[c];
      a1 += xx * w1v[c];
    }
  }
  __shared__ float s0[256];
  __shared__ float s1[256];
  s0[tid] = a0; s1[tid] = a1;
  __syncthreads();
#pragma unroll
  for (int off = 128; off > 0; off >>= 1) {
    if (tid < off) { s0[tid] += s0[tid + off]; s1[tid] += s1[tid + off]; }
    __syncthreads();
  }
  if (tid == 0) {
    out[2 * b + 0] = s0[0] + bout[0];
    out[2 * b + 1] = s1[0] + bout[1];
  }
}

// ---------------------------------------------------------------------------
// Launch
// ---------------------------------------------------------------------------
extern "C" void kernel_launch(void* const* d_in, const int* in_sizes, int n_in,
                              void* d_out, int out_size) {
  (void)in_sizes; (void)n_in; (void)out_size;
  const float* x    = (const float*)d_in[0];
  const float* W1   = (const float*)d_in[1];
  const float* b1   = (const float*)d_in[2];
  const float* W2   = (const float*)d_in[3];
  const float* b2   = (const float*)d_in[4];
  const float* Wout = (const float*)d_in[5];
  const float* bout = (const float*)d_in[6];
  float* out = (float*)d_out;

  cudaFuncSetAttribute(gemm_fp16_kernel,
                       cudaFuncAttributeMaxDynamicSharedMemorySize,
                       GEMM_DYN_SMEM);

  // Device address of g_colAdd (host-side __device__ symbol use is UB).
  float* colAddPtr = nullptr;
  cudaGetSymbolAddress((void**)&colAddPtr, g_colAdd);

  uint32_t kno[2][2], kph[2][2];
  for (int li = 0; li < 2; ++li) {
    threefry2x32(0u, 42u, 0u, (uint32_t)(2 * li),     kno[li][0], kno[li][1]);
    threefry2x32(0u, 42u, 0u, (uint32_t)(2 * li + 1), kph[li][0], kph[li][1]);
  }

  const dim3 ggrid(HDIM / TN, BATCH / TM);  // 8 x 64

  // Layer 0 (K = 1024); bias = b1 (no thermal offset yet).
  convert_w_kernel<<<2048, 256>>>(W1, 2048 * 1024 / 4);
  tanh_in_kernel<<<8192, 256>>>(x);
  gemm_fp16_kernel<<<ggrid, 512, GEMM_DYN_SMEM>>>(b1, 1024,
                                                  kno[0][0], kno[0][1]);
  colsum_part_kernel<<<512, 256>>>();
  colsum_reduce_kernel<<<8, 256>>>();
  thermal_matvec_kernel<<<16, 128>>>(0, 1);
  tnw_kernel<<<256, 256>>>(W2, b2);
  finalize_kernel<<<16384, 256>>>(kph[0][0], kph[0][1]);

  // Layer 1 (K = 2048); bias = b2 + tn@W2^T (exact fp32), A offset-free.
  convert_w_kernel<<<4096, 256>>>(W2, 2048 * 2048 / 4);
  gemm_fp16_kernel<<<ggrid, 512, GEMM_DYN_SMEM>>>(colAddPtr, 2048,
                                                  kno[1][0], kno[1][1]);
  colsum_part_kernel<<<512, 256>>>();
  colsum_reduce_kernel<<<8, 256>>>();
  thermal_matvec_kernel<<<16, 128>>>(1, 0);

  finalize_out_kernel<<<8192, 256>>>(Wout, bout, out, kph[1][0], kph[1][1]);
}